// round 4
// baseline (speedup 1.0000x reference)
#include <cuda_runtime.h>
#include <math.h>

#define T_DIM 512
#define B_DIM 32
#define V_DIM 4096
#define S_DIM 64
#define L_DIM 129              // 2*S + 1
#define LPW   65               // stored probs per (b,t): blank + 64 labels

#define LOG2E 1.4426950408889634f
#define LN2   0.6931471805599453f

// Scratch (zero-init at load; flags/done are reset in-kernel each run).
__device__ float g_p[(size_t)B_DIM * T_DIM * LPW];
__device__ float g_nll[B_DIM];
__device__ int   g_flag[B_DIM * T_DIM];
__device__ int   g_done;

__device__ __forceinline__ float ex2(float x) {
    float y; asm("ex2.approx.f32 %0, %1;" : "=f"(y) : "f"(x)); return y;
}
__device__ __forceinline__ float lg2(float x) {
    float y; asm("lg2.approx.f32 %0, %1;" : "=f"(y) : "f"(x)); return y;
}
__device__ __forceinline__ unsigned warp_max_u32(unsigned v) {
    unsigned r;
    asm("redux.sync.max.u32 %0, %1, 0xffffffff;" : "=r"(r) : "r"(v));
    return r;
}
__device__ __forceinline__ void st_release(int* p, int v) {
    asm volatile("st.release.gpu.global.b32 [%0], %1;" :: "l"(p), "r"(v) : "memory");
}
__device__ __forceinline__ int ld_acquire(const int* p) {
    int v;
    asm volatile("ld.acquire.gpu.global.b32 %0, [%1];" : "=r"(v) : "l"(p) : "memory");
    return v;
}

// ---------------------------------------------------------------------------
// Fused kernel. Blocks 0..31: per-batch alpha consumers (warp 0 computes).
// Blocks 32..: per-(t,b)-row softmax+gather producers, flag each row done.
// ---------------------------------------------------------------------------
__global__ __launch_bounds__(256) void k_fused(
    const float* __restrict__ acts, const int* __restrict__ labels,
    const int* __restrict__ input_len, const int* __restrict__ target_len,
    float* __restrict__ out) {
    const int tid = threadIdx.x;

    if (blockIdx.x >= B_DIM) {
        // ================= producer: softmax row (t,b) =================
        const int row = blockIdx.x - B_DIM;       // t*B + b
        const int t   = row / B_DIM;
        const int b   = row - t * B_DIM;
        const float* __restrict__ x = acts + (size_t)row * V_DIM;

        const float4* __restrict__ x4 = reinterpret_cast<const float4*>(x);
        float s = 0.0f;
        #pragma unroll
        for (int k = 0; k < 4; ++k) {
            float4 r = __ldcs(&x4[tid + 256 * k]);
            s += ex2(r.x * LOG2E) + ex2(r.y * LOG2E)
               + ex2(r.z * LOG2E) + ex2(r.w * LOG2E);
        }

        __shared__ float s_s[8];
        __shared__ float s_bcast;
        #pragma unroll
        for (int o = 16; o; o >>= 1) s += __shfl_xor_sync(0xffffffffu, s, o);
        if ((tid & 31) == 0) s_s[tid >> 5] = s;
        __syncthreads();
        if (tid < 32) {
            float v = (tid < 8) ? s_s[tid] : 0.0f;
            #pragma unroll
            for (int o = 4; o; o >>= 1) v += __shfl_xor_sync(0xffffffffu, v, o);
            if (tid == 0) s_bcast = lg2(v);
        }
        __syncthreads();
        const float log2sum = s_bcast;

        if (tid < LPW) {
            const int cls = (tid == 0) ? 0 : __ldg(&labels[b * S_DIM + tid - 1]);
            g_p[((size_t)b * T_DIM + t) * LPW + tid] =
                ex2(x[cls] * LOG2E - log2sum);
        }
        __syncthreads();                          // all 65 writes done
        if (tid == 0) st_release(&g_flag[b * T_DIM + t], 1);
        return;
    }

    // ================= consumer: alpha recursion for batch b =================
    const int b    = blockIdx.x;
    const int lane = tid & 31;
    __shared__ float sA[L_DIM + 3];

    if (tid < 32) {
        const float* __restrict__ base = g_p + (size_t)b * T_DIM * LPW;
        const int* __restrict__   flg  = g_flag + b * T_DIM;

        const int j1 = 2 * lane + 1;
        const int j2 = 2 * lane + 2;
        const int* lab = labels + b * S_DIM;
        const bool sk1 = (lane >= 1) && (__ldg(&lab[2 * lane]) != __ldg(&lab[2 * lane - 1]));
        const bool sk3 = (__ldg(&lab[2 * lane + 1]) != __ldg(&lab[2 * lane]));
        const int len = __ldg(&input_len[b]);

        // Wait for row t=0, init alphas.
        while (__any_sync(0xffffffffu, ld_acquire(&flg[0]) == 0)) __nanosleep(64);
        float a0 = (lane == 0) ? __ldg(&base[0]) : 0.0f;
        float a1 = (lane == 0) ? __ldg(&base[1]) : 0.0f;
        float a2 = 0.0f, a3 = 0.0f, a4 = 0.0f;
        int   E  = 0;

        auto step = [&](float pb, float pl1, float pl2) {
            float p3 = __shfl_up_sync(0xffffffffu, a3, 1);
            p3 = (lane == 0) ? 0.0f : p3;
            const float n0 = (a0 + p3) * pb;
            const float n1 = (a1 + a0 + (sk1 ? p3 : 0.0f)) * pl1;
            const float n2 = (a2 + a1) * pb;
            const float n3 = (a3 + a2 + (sk3 ? a1 : 0.0f)) * pl2;
            a4 = (a4 + a3) * pb;   // real only on lane31; junk elsewhere (benign)
            a0 = n0; a1 = n1; a2 = n2; a3 = n3;
        };
        auto wait4 = [&](int t0) {
            while (__any_sync(0xffffffffu,
                   ld_acquire(&flg[t0 + (lane & 3)]) == 0)) __nanosleep(64);
        };

        float P0[4], P1[4], P2[4], N0[4], N1[4], N2[4];
        int t = 1;
        const int ngroups = (len - 1) >> 2;

        if (ngroups > 0) {
            wait4(t);
            #pragma unroll
            for (int i = 0; i < 4; ++i) {
                const float* r = base + (t + i) * LPW;
                P0[i] = __ldg(r); P1[i] = __ldg(r + j1); P2[i] = __ldg(r + j2);
            }
        }
        #pragma unroll 1
        for (int g = 0; g < ngroups; ++g) {
            const bool pre = (g + 1 < ngroups);
            if (pre) {
                wait4(t + 4);
                #pragma unroll
                for (int i = 0; i < 4; ++i) {
                    const float* r = base + (t + 4 + i) * LPW;
                    N0[i] = __ldg(r); N1[i] = __ldg(r + j1); N2[i] = __ldg(r + j2);
                }
            }
            step(P0[0], P1[0], P2[0]);
            step(P0[1], P1[1], P2[1]);
            step(P0[2], P1[2], P2[2]);
            step(P0[3], P1[3], P2[3]);

            float m = fmaxf(fmaxf(a0, a1), fmaxf(fmaxf(a2, a3), a4));
            const unsigned gmax = warp_max_u32(__float_as_uint(m));
            if (gmax) {
                const int e = (int)(gmax >> 23);
                E += e - 127;
                const float sc = __uint_as_float((unsigned)(254 - e) << 23);
                a0 *= sc; a1 *= sc; a2 *= sc; a3 *= sc; a4 *= sc;
            }
            if (pre) {
                #pragma unroll
                for (int i = 0; i < 4; ++i) { P0[i] = N0[i]; P1[i] = N1[i]; P2[i] = N2[i]; }
            }
            t += 4;
        }
        #pragma unroll 1
        for (; t < len; ++t) {
            while (__any_sync(0xffffffffu, ld_acquire(&flg[t]) == 0)) __nanosleep(64);
            const float* r = base + t * LPW;
            step(__ldg(r), __ldg(r + j1), __ldg(r + j2));
        }

        // Stash and finalize per-batch NLL.
        sA[4 * lane + 0] = a0;
        sA[4 * lane + 1] = a1;
        sA[4 * lane + 2] = a2;
        sA[4 * lane + 3] = a3;
        if (lane == 31) sA[128] = a4;
        __syncwarp();
        if (lane == 0) {
            int hi = 2 * __ldg(&target_len[b]);
            if (hi > L_DIM - 1) hi = L_DIM - 1;
            int lo = hi - 1; if (lo < 0) lo = 0;
            const float sum = sA[hi] + sA[lo];
            float v = -(lg2(sum) + (float)E) * LN2;
            if (!isfinite(v) || v > 1e29f || sum <= 0.0f) v = 0.0f;
            g_nll[b] = v;
        }
    }

    // All warps: wait until every row of this batch is flagged (producers
    // always flag all T rows), so the reset below cannot race a late producer.
    {
        const int* __restrict__ flg = g_flag + b * T_DIM;
        for (int t = tid; t < T_DIM; t += 256)
            while (ld_acquire(&flg[t]) == 0) __nanosleep(128);
    }
    __syncthreads();
    // Reset flags for the next graph replay.
    for (int t = tid; t < T_DIM; t += 256) g_flag[b * T_DIM + t] = 0;

    if (tid == 0) {
        __threadfence();
        const int old = atomicAdd(&g_done, 1);
        if (old == B_DIM - 1) {                    // last block: reduce + output
            __threadfence();
            float s = 0.0f;
            #pragma unroll
            for (int i = 0; i < B_DIM; ++i)
                s += ((volatile float*)g_nll)[i];
            out[0] = s;
            g_done = 0;                            // reset for next replay
        }
    }
}

extern "C" void kernel_launch(void* const* d_in, const int* in_sizes, int n_in,
                              void* d_out, int out_size) {
    const float* acts   = (const float*)d_in[0];
    const int*   labels = (const int*)d_in[1];
    const int*   ilen   = (const int*)d_in[2];
    const int*   tlen   = (const int*)d_in[3];
    (void)in_sizes; (void)n_in; (void)out_size;

    k_fused<<<B_DIM + T_DIM * B_DIM, 256>>>(acts, labels, ilen, tlen,
                                            (float*)d_out);
}

// round 5
// speedup vs baseline: 1.0943x; 1.0943x over previous
#include <cuda_runtime.h>
#include <math.h>

#define T_DIM 512
#define B_DIM 32
#define V_DIM 4096
#define S_DIM 64
#define L_DIM 129              // 2*S + 1
#define LPW   65               // probs per (b,t): blank + 64 labels
#define PSTR  68               // padded row stride (16B-aligned)

#define LOG2E 1.4426950408889634f
#define LN2   0.6931471805599453f

// Scratch (zero-init at load; flags/done reset in-kernel each run).
__device__ float g_p[(size_t)B_DIM * T_DIM * PSTR];
__device__ float g_nll[B_DIM];
__device__ int   g_flag[B_DIM * T_DIM];
__device__ int   g_done;

__device__ __forceinline__ float ex2(float x) {
    float y; asm("ex2.approx.f32 %0, %1;" : "=f"(y) : "f"(x)); return y;
}
__device__ __forceinline__ float lg2(float x) {
    float y; asm("lg2.approx.f32 %0, %1;" : "=f"(y) : "f"(x)); return y;
}
__device__ __forceinline__ unsigned warp_max_u32(unsigned v) {
    unsigned r;
    asm("redux.sync.max.u32 %0, %1, 0xffffffff;" : "=r"(r) : "r"(v));
    return r;
}
__device__ __forceinline__ void st_release(int* p, int v) {
    asm volatile("st.release.gpu.global.b32 [%0], %1;" :: "l"(p), "r"(v) : "memory");
}
__device__ __forceinline__ int ld_acquire(const int* p) {
    int v;
    asm volatile("ld.acquire.gpu.global.b32 %0, [%1];" : "=r"(v) : "l"(p) : "memory");
    return v;
}
__device__ __forceinline__ void cp16(unsigned dst_s, const void* src) {
    asm volatile("cp.async.ca.shared.global [%0], [%1], 16;"
                 :: "r"(dst_s), "l"(src));
}

// ---------------------------------------------------------------------------
// Fused kernel. Blocks 0..31: per-batch alpha consumers (warp 0 computes,
// cp.async double-buffered smem ring keeps registers low).
// Blocks 32..: per-(t,b)-row softmax producers; rows with t >= len[b] are
// skipped entirely (their probs are never consumed) -- ~25% DRAM saved.
// ---------------------------------------------------------------------------
__global__ __launch_bounds__(256, 7) void k_fused(
    const float* __restrict__ acts, const int* __restrict__ labels,
    const int* __restrict__ input_len, const int* __restrict__ target_len,
    float* __restrict__ out) {
    const int tid = threadIdx.x;

    __shared__ float ring[8][PSTR];     // consumer: 2 groups x 4 rows
    __shared__ float sA[L_DIM + 3];
    __shared__ float s_s[8];
    __shared__ float s_bcast;

    if (blockIdx.x >= B_DIM) {
        // ================= producer: softmax row (t,b) =================
        const int row = blockIdx.x - B_DIM;       // t*B + b
        const int t   = row / B_DIM;
        const int b   = row - t * B_DIM;

        if (t >= __ldg(&input_len[b])) {          // dead row: flag & exit
            if (tid == 0) st_release(&g_flag[b * T_DIM + t], 1);
            return;
        }

        const float* __restrict__ x = acts + (size_t)row * V_DIM;
        const float4* __restrict__ x4 = reinterpret_cast<const float4*>(x);
        float s = 0.0f;
        #pragma unroll
        for (int k = 0; k < 4; ++k) {
            float4 r = __ldcs(&x4[tid + 256 * k]);
            s += ex2(r.x * LOG2E) + ex2(r.y * LOG2E)
               + ex2(r.z * LOG2E) + ex2(r.w * LOG2E);
        }
        #pragma unroll
        for (int o = 16; o; o >>= 1) s += __shfl_xor_sync(0xffffffffu, s, o);
        if ((tid & 31) == 0) s_s[tid >> 5] = s;
        __syncthreads();
        if (tid < 32) {
            float v = (tid < 8) ? s_s[tid] : 0.0f;
            #pragma unroll
            for (int o = 4; o; o >>= 1) v += __shfl_xor_sync(0xffffffffu, v, o);
            if (tid == 0) s_bcast = lg2(v);
        }
        __syncthreads();
        const float log2sum = s_bcast;

        if (tid < LPW) {
            const int cls = (tid == 0) ? 0 : __ldg(&labels[b * S_DIM + tid - 1]);
            g_p[((size_t)b * T_DIM + t) * PSTR + tid] =
                ex2(x[cls] * LOG2E - log2sum);
        }
        __syncthreads();
        if (tid == 0) st_release(&g_flag[b * T_DIM + t], 1);
        return;
    }

    // ================= consumer: alpha recursion for batch b =================
    const int b    = blockIdx.x;
    const int lane = tid & 31;

    if (tid < 32) {
        const float* __restrict__ base = g_p + (size_t)b * T_DIM * PSTR;
        const int* __restrict__   flg  = g_flag + b * T_DIM;

        const int j1 = 2 * lane + 1;
        const int j2 = 2 * lane + 2;
        const int* lab = labels + b * S_DIM;
        const bool sk1 = (lane >= 1) && (__ldg(&lab[2 * lane]) != __ldg(&lab[2 * lane - 1]));
        const bool sk3 = (__ldg(&lab[2 * lane + 1]) != __ldg(&lab[2 * lane]));
        const int len = __ldg(&input_len[b]);

        while (__any_sync(0xffffffffu, ld_acquire(&flg[0]) == 0)) __nanosleep(64);
        __syncwarp();
        float a0 = (lane == 0) ? __ldg(&base[0]) : 0.0f;
        float a1 = (lane == 0) ? __ldg(&base[1]) : 0.0f;
        float a2 = 0.0f, a3 = 0.0f, a4 = 0.0f;
        int   E  = 0;

        auto step = [&](float pb, float pl1, float pl2) {
            float p3 = __shfl_up_sync(0xffffffffu, a3, 1);
            p3 = (lane == 0) ? 0.0f : p3;
            const float n0 = (a0 + p3) * pb;
            const float n1 = (a1 + a0 + (sk1 ? p3 : 0.0f)) * pl1;
            const float n2 = (a2 + a1) * pb;
            const float n3 = (a3 + a2 + (sk3 ? a1 : 0.0f)) * pl2;
            a4 = (a4 + a3) * pb;   // real only on lane31; junk elsewhere (benign)
            a0 = n0; a1 = n1; a2 = n2; a3 = n3;
        };
        auto wait4 = [&](int t0) {
            const int* f = flg + t0 + (lane & 3);
            while (__any_sync(0xffffffffu, ld_acquire(f) == 0)) __nanosleep(64);
            __syncwarp();
        };
        // Fetch 4 rows [t0..t0+3] into ring[buf*4..buf*4+3] via cp.async.
        auto fetch4 = [&](int buf, int t0) {
            const char* src = (const char*)(base + (size_t)t0 * PSTR);
            unsigned dst = (unsigned)__cvta_generic_to_shared(&ring[buf * 4][0]);
            #pragma unroll
            for (int c = lane; c < 68; c += 32) {       // 17 chunks x 4 rows
                const int r   = c / 17;
                const int off = c - r * 17;
                cp16(dst + (unsigned)(r * PSTR + off * 4) * 4u,
                     src + ((size_t)r * PSTR * 4 + (size_t)off * 16));
            }
        };

        int t = 1;
        const int ngroups = (len - 1) >> 2;

        if (ngroups > 0) {
            wait4(1);
            fetch4(0, 1);
            asm volatile("cp.async.commit_group;");
        }
        #pragma unroll 1
        for (int g = 0; g < ngroups; ++g) {
            if (g + 1 < ngroups) {
                wait4(t + 4);
                fetch4((g + 1) & 1, t + 4);
            }
            asm volatile("cp.async.commit_group;");     // (possibly empty)
            asm volatile("cp.async.wait_group 1;");     // group g data ready
            __syncwarp();

            const float* rp = &ring[(g & 1) * 4][0];
            #pragma unroll
            for (int i = 0; i < 4; ++i)
                step(rp[i * PSTR], rp[i * PSTR + j1], rp[i * PSTR + j2]);

            float m = fmaxf(fmaxf(a0, a1), fmaxf(fmaxf(a2, a3), a4));
            const unsigned gmax = warp_max_u32(__float_as_uint(m));
            if (gmax) {
                const int e = (int)(gmax >> 23);
                E += e - 127;
                const float sc = __uint_as_float((unsigned)(254 - e) << 23);
                a0 *= sc; a1 *= sc; a2 *= sc; a3 *= sc; a4 *= sc;
            }
            t += 4;
        }
        #pragma unroll 1
        for (; t < len; ++t) {                          // <=3 tail steps
            while (__any_sync(0xffffffffu, ld_acquire(&flg[t]) == 0)) __nanosleep(64);
            __syncwarp();
            const float* r = base + (size_t)t * PSTR;
            step(__ldg(r), __ldg(r + j1), __ldg(r + j2));
        }

        sA[4 * lane + 0] = a0;
        sA[4 * lane + 1] = a1;
        sA[4 * lane + 2] = a2;
        sA[4 * lane + 3] = a3;
        if (lane == 31) sA[128] = a4;
        __syncwarp();
        if (lane == 0) {
            int hi = 2 * __ldg(&target_len[b]);
            if (hi > L_DIM - 1) hi = L_DIM - 1;
            int lo = hi - 1; if (lo < 0) lo = 0;
            const float sum = sA[hi] + sA[lo];
            float v = -(lg2(sum) + (float)E) * LN2;
            if (!isfinite(v) || v > 1e29f || sum <= 0.0f) v = 0.0f;
            g_nll[b] = v;
        }
    }

    // All threads: wait for every row flagged (producers always flag all T),
    // then reset flags for the next graph replay.
    {
        const int* __restrict__ flg = g_flag + b * T_DIM;
        for (int t = tid; t < T_DIM; t += 256)
            while (ld_acquire(&flg[t]) == 0) __nanosleep(128);
    }
    __syncthreads();
    for (int t = tid; t < T_DIM; t += 256) g_flag[b * T_DIM + t] = 0;

    if (tid == 0) {
        __threadfence();
        const int old = atomicAdd(&g_done, 1);
        if (old == B_DIM - 1) {
            __threadfence();
            float s = 0.0f;
            #pragma unroll
            for (int i = 0; i < B_DIM; ++i)
                s += ((volatile float*)g_nll)[i];
            out[0] = s;
            g_done = 0;
        }
    }
}

extern "C" void kernel_launch(void* const* d_in, const int* in_sizes, int n_in,
                              void* d_out, int out_size) {
    const float* acts   = (const float*)d_in[0];
    const int*   labels = (const int*)d_in[1];
    const int*   ilen   = (const int*)d_in[2];
    const int*   tlen   = (const int*)d_in[3];
    (void)in_sizes; (void)n_in; (void)out_size;

    k_fused<<<B_DIM + T_DIM * B_DIM, 256>>>(acts, labels, ilen, tlen,
                                            (float*)d_out);
}

// round 6
// speedup vs baseline: 1.4255x; 1.3026x over previous
#include <cuda_runtime.h>
#include <math.h>

#define T_DIM 512
#define B_DIM 32
#define V_DIM 4096
#define S_DIM 64
#define L_DIM 129              // 2*S + 1
#define LPW   65               // probs per (b,t): blank + 64 labels

#define LOG2E 1.4426950408889634f
#define LN2   0.6931471805599453f

// Scratch (zero-init at load; g_done reset in-kernel each run).
__device__ float g_p[(size_t)B_DIM * T_DIM * LPW];
__device__ float g_nll[B_DIM];
__device__ int   g_done;

__device__ __forceinline__ float ex2(float x) {
    float y; asm("ex2.approx.f32 %0, %1;" : "=f"(y) : "f"(x)); return y;
}
__device__ __forceinline__ float lg2(float x) {
    float y; asm("lg2.approx.f32 %0, %1;" : "=f"(y) : "f"(x)); return y;
}
__device__ __forceinline__ unsigned warp_max_u32(unsigned v) {
    unsigned r;
    asm("redux.sync.max.u32 %0, %1, 0xffffffff;" : "=r"(r) : "r"(v));
    return r;
}

// ---------------------------------------------------------------------------
// Kernel 1: per (t,b) row: one-pass sum(exp) + gather 65 linear probs.
// Rows with t >= input_len[b] are never consumed -> skip entirely (~25% DRAM).
// ---------------------------------------------------------------------------
__global__ __launch_bounds__(256) void k_lse_gather(
    const float* __restrict__ acts, const int* __restrict__ labels,
    const int* __restrict__ input_len) {
    const int row = blockIdx.x;            // t*B + b
    const int t   = row / B_DIM;
    const int b   = row - t * B_DIM;
    if (t >= __ldg(&input_len[b])) return; // dead row

    const float* __restrict__ x = acts + (size_t)row * V_DIM;
    const int tid = threadIdx.x;

    const float4* __restrict__ x4 = reinterpret_cast<const float4*>(x);
    float s = 0.0f;
    #pragma unroll
    for (int k = 0; k < 4; ++k) {
        float4 r = __ldcs(&x4[tid + 256 * k]);   // stream, evict-first
        s += ex2(r.x * LOG2E) + ex2(r.y * LOG2E)
           + ex2(r.z * LOG2E) + ex2(r.w * LOG2E);
    }

    __shared__ float s_s[8];
    __shared__ float s_bcast;
    #pragma unroll
    for (int o = 16; o; o >>= 1) s += __shfl_xor_sync(0xffffffffu, s, o);
    if ((tid & 31) == 0) s_s[tid >> 5] = s;
    __syncthreads();
    if (tid < 32) {
        float v = (tid < 8) ? s_s[tid] : 0.0f;
        #pragma unroll
        for (int o = 4; o; o >>= 1) v += __shfl_xor_sync(0xffffffffu, v, o);
        if (tid == 0) s_bcast = lg2(v);
    }
    __syncthreads();
    const float log2sum = s_bcast;

    if (tid < LPW) {
        const int cls = (tid == 0) ? 0 : __ldg(&labels[b * S_DIM + tid - 1]);
        g_p[((size_t)b * T_DIM + t) * LPW + tid] =
            ex2(x[cls] * LOG2E - log2sum);
    }
}

// ---------------------------------------------------------------------------
// Kernel 2: scaled linear-domain CTC alpha, one block per batch.
// 128 threads: all 4 warps preload the (len x 65) slab to smem, then warp 0
// runs the register recursion with a register double-buffer of the next
// group's 12 probs (LDS latency off the serial chain). Renorm every 4 steps
// via redux.sync. Last block to finish reduces the 32 NLLs into out[0].
// ---------------------------------------------------------------------------
__global__ __launch_bounds__(128) void k_alpha(
    const int* __restrict__ labels,
    const int* __restrict__ input_len,
    const int* __restrict__ target_len,
    float* __restrict__ out) {
    extern __shared__ float sp[];                 // up to T_DIM * LPW floats
    const int b   = blockIdx.x;
    const int tid = threadIdx.x;
    const int len = __ldg(&input_len[b]);

    // Cooperative preload of live rows [0, len): contiguous float4 copies.
    {
        const float4* __restrict__ src =
            reinterpret_cast<const float4*>(g_p + (size_t)b * T_DIM * LPW);
        float4* dst = reinterpret_cast<float4*>(sp);
        const int n4 = (len * LPW + 3) >> 2;
        #pragma unroll 4
        for (int i = tid; i < n4; i += 128) dst[i] = src[i];
    }
    __syncthreads();

    if (tid < 32) {
        const int lane = tid;
        const int j1 = 2 * lane + 1;
        const int j2 = 2 * lane + 2;
        const int* lab = labels + b * S_DIM;
        const bool sk1 = (lane >= 1) && (__ldg(&lab[2 * lane]) != __ldg(&lab[2 * lane - 1]));
        const bool sk3 = (__ldg(&lab[2 * lane + 1]) != __ldg(&lab[2 * lane]));

        float a0 = (lane == 0) ? sp[0] : 0.0f;
        float a1 = (lane == 0) ? sp[1] : 0.0f;
        float a2 = 0.0f, a3 = 0.0f, a4 = 0.0f;
        int   E  = 0;

        auto step = [&](float pb, float pl1, float pl2) {
            float p3 = __shfl_up_sync(0xffffffffu, a3, 1);
            p3 = (lane == 0) ? 0.0f : p3;
            const float n0 = (a0 + p3) * pb;
            const float n1 = (a1 + a0 + (sk1 ? p3 : 0.0f)) * pl1;
            const float n2 = (a2 + a1) * pb;
            const float n3 = (a3 + a2 + (sk3 ? a1 : 0.0f)) * pl2;
            a4 = (a4 + a3) * pb;   // real only on lane31; junk elsewhere (benign)
            a0 = n0; a1 = n1; a2 = n2; a3 = n3;
        };

        float C0[4], C1[4], C2[4], N0[4], N1[4], N2[4];
        int t = 1;
        const int ngroups = (len - 1) >> 2;

        if (ngroups > 0) {
            #pragma unroll
            for (int i = 0; i < 4; ++i) {
                const float* r = sp + (1 + i) * LPW;
                C0[i] = r[0]; C1[i] = r[j1]; C2[i] = r[j2];
            }
        }
        #pragma unroll 1
        for (int g = 0; g < ngroups; ++g) {
            if (g + 1 < ngroups) {                  // prefetch next group
                #pragma unroll
                for (int i = 0; i < 4; ++i) {
                    const float* r = sp + (t + 4 + i) * LPW;
                    N0[i] = r[0]; N1[i] = r[j1]; N2[i] = r[j2];
                }
            }
            step(C0[0], C1[0], C2[0]);
            step(C0[1], C1[1], C2[1]);
            step(C0[2], C1[2], C2[2]);
            step(C0[3], C1[3], C2[3]);

            float m = fmaxf(fmaxf(a0, a1), fmaxf(fmaxf(a2, a3), a4));
            const unsigned gmax = warp_max_u32(__float_as_uint(m));
            if (gmax) {
                const int e = (int)(gmax >> 23);
                E += e - 127;
                const float sc = __uint_as_float((unsigned)(254 - e) << 23);
                a0 *= sc; a1 *= sc; a2 *= sc; a3 *= sc; a4 *= sc;
            }
            #pragma unroll
            for (int i = 0; i < 4; ++i) { C0[i] = N0[i]; C1[i] = N1[i]; C2[i] = N2[i]; }
            t += 4;
        }
        #pragma unroll 1
        for (; t < len; ++t) {                      // <=3 tail steps
            const float* r = sp + t * LPW;
            step(r[0], r[j1], r[j2]);
        }

        // Stash alphas in smem (slab no longer needed) and finalize.
        __syncwarp();
        sp[4 * lane + 0] = a0;
        sp[4 * lane + 1] = a1;
        sp[4 * lane + 2] = a2;
        sp[4 * lane + 3] = a3;
        if (lane == 31) sp[128] = a4;
        __syncwarp();

        if (lane == 0) {
            int hi = 2 * __ldg(&target_len[b]);
            if (hi > L_DIM - 1) hi = L_DIM - 1;
            int lo = hi - 1; if (lo < 0) lo = 0;
            const float sum = sp[hi] + sp[lo];
            float v = -(lg2(sum) + (float)E) * LN2;
            if (!isfinite(v) || v > 1e29f || sum <= 0.0f) v = 0.0f;
            g_nll[b] = v;

            __threadfence();
            const int old = atomicAdd(&g_done, 1);
            if (old == B_DIM - 1) {                 // last block: reduce
                __threadfence();
                float s = 0.0f;
                #pragma unroll
                for (int i = 0; i < B_DIM; ++i)
                    s += ((volatile float*)g_nll)[i];
                out[0] = s;
                g_done = 0;                         // reset for next replay
            }
        }
    }
}

extern "C" void kernel_launch(void* const* d_in, const int* in_sizes, int n_in,
                              void* d_out, int out_size) {
    const float* acts   = (const float*)d_in[0];
    const int*   labels = (const int*)d_in[1];
    const int*   ilen   = (const int*)d_in[2];
    const int*   tlen   = (const int*)d_in[3];
    (void)in_sizes; (void)n_in; (void)out_size;

    const int smem_bytes = T_DIM * LPW * (int)sizeof(float);   // 133120
    cudaFuncSetAttribute(k_alpha, cudaFuncAttributeMaxDynamicSharedMemorySize,
                         smem_bytes);

    k_lse_gather<<<T_DIM * B_DIM, 256>>>(acts, labels, ilen);
    k_alpha<<<B_DIM, 128, smem_bytes>>>(labels, ilen, tlen, (float*)d_out);
}

// round 8
// speedup vs baseline: 1.5896x; 1.1151x over previous
#include <cuda_runtime.h>
#include <math.h>

#define T_DIM 512
#define B_DIM 32
#define V_DIM 4096
#define S_DIM 64
#define L_DIM 129              // 2*S + 1
#define LPW   65               // probs per (b,t): blank + 64 labels

#define LOG2E 1.4426950408889634f
#define LN2   0.6931471805599453f

// Scratch (zero-init at load; g_done reset in-kernel each run).
__device__ float g_p[(size_t)B_DIM * T_DIM * LPW];
__device__ float g_nll[B_DIM];
__device__ int   g_done;

__device__ __forceinline__ float ex2(float x) {
    float y; asm("ex2.approx.f32 %0, %1;" : "=f"(y) : "f"(x)); return y;
}
__device__ __forceinline__ float lg2(float x) {
    float y; asm("lg2.approx.f32 %0, %1;" : "=f"(y) : "f"(x)); return y;
}
__device__ __forceinline__ unsigned warp_max_u32(unsigned v) {
    unsigned r;
    asm("redux.sync.max.u32 %0, %1, 0xffffffff;" : "=r"(r) : "r"(v));
    return r;
}

// ---------------------------------------------------------------------------
// Kernel 1: per (t,b) row: one-pass sum(exp) + gather 65 linear probs.
// Rows with t >= input_len[b] are never consumed -> skipped (~25% DRAM).
// ---------------------------------------------------------------------------
__global__ __launch_bounds__(256) void k_lse_gather(
    const float* __restrict__ acts, const int* __restrict__ labels,
    const int* __restrict__ input_len) {
    const int row = blockIdx.x;            // t*B + b
    const int t   = row / B_DIM;
    const int b   = row - t * B_DIM;
    if (t >= __ldg(&input_len[b])) return; // dead row

    const float* __restrict__ x = acts + (size_t)row * V_DIM;
    const int tid = threadIdx.x;

    const float4* __restrict__ x4 = reinterpret_cast<const float4*>(x);
    float s = 0.0f;
    #pragma unroll
    for (int k = 0; k < 4; ++k) {
        float4 r = __ldcs(&x4[tid + 256 * k]);   // stream, evict-first
        s += ex2(r.x * LOG2E) + ex2(r.y * LOG2E)
           + ex2(r.z * LOG2E) + ex2(r.w * LOG2E);
    }

    __shared__ float s_s[8];
    __shared__ float s_bcast;
    #pragma unroll
    for (int o = 16; o; o >>= 1) s += __shfl_xor_sync(0xffffffffu, s, o);
    if ((tid & 31) == 0) s_s[tid >> 5] = s;
    __syncthreads();
    if (tid < 32) {
        float v = (tid < 8) ? s_s[tid] : 0.0f;
        #pragma unroll
        for (int o = 4; o; o >>= 1) v += __shfl_xor_sync(0xffffffffu, v, o);
        if (tid == 0) s_bcast = lg2(v);
    }
    __syncthreads();
    const float log2sum = s_bcast;

    if (tid < LPW) {
        const int cls = (tid == 0) ? 0 : __ldg(&labels[b * S_DIM + tid - 1]);
        g_p[((size_t)b * T_DIM + t) * LPW + tid] =
            ex2(x[cls] * LOG2E - log2sum);
    }
}

// ---------------------------------------------------------------------------
// Kernel 2: scaled linear-domain CTC alpha, one block per batch.
// Software-pipelined: n3 computed FIRST each step, shfl(n3) issued
// immediately for the NEXT step -> shfl latency off the 1-step chain.
// Renorm every 4 steps (required: probs can be ~2^-19/step; 8-step spacing
// underflows). 8-step unrolled groups, double-buffered prob prefetch.
// Last block reduces the 32 NLLs into out[0].
// ---------------------------------------------------------------------------
__global__ __launch_bounds__(128) void k_alpha(
    const int* __restrict__ labels,
    const int* __restrict__ input_len,
    const int* __restrict__ target_len,
    float* __restrict__ out) {
    extern __shared__ float sp[];                 // up to T_DIM * LPW floats
    const int b   = blockIdx.x;
    const int tid = threadIdx.x;
    const int len = __ldg(&input_len[b]);

    // Cooperative preload of live rows [0, len).
    {
        const float4* __restrict__ src =
            reinterpret_cast<const float4*>(g_p + (size_t)b * T_DIM * LPW);
        float4* dst = reinterpret_cast<float4*>(sp);
        const int n4 = (len * LPW + 3) >> 2;
        #pragma unroll 4
        for (int i = tid; i < n4; i += 128) dst[i] = src[i];
    }
    __syncthreads();

    if (tid < 32) {
        const int lane = tid;
        const int j1 = 2 * lane + 1;
        const int j2 = 2 * lane + 2;
        const int* lab = labels + b * S_DIM;
        const bool sk1 = (lane >= 1) && (__ldg(&lab[2 * lane]) != __ldg(&lab[2 * lane - 1]));
        const bool sk3 = (__ldg(&lab[2 * lane + 1]) != __ldg(&lab[2 * lane]));

        float a0 = (lane == 0) ? sp[0] : 0.0f;
        float a1 = (lane == 0) ? sp[1] : 0.0f;
        float a2 = 0.0f, a3 = 0.0f, a4 = 0.0f;
        float p3 = 0.0f;                    // neighbor's a3 (all zero at t=0)
        int   E  = 0;

        // Pipelined step: n3 first, shfl immediately (result feeds NEXT step).
        auto step = [&](float pb, float pl1, float pl2) {
            const float n3 = (a3 + a2 + (sk3 ? a1 : 0.0f)) * pl2;
            const float t3 = __shfl_up_sync(0xffffffffu, n3, 1);
            const float n0 = (a0 + p3) * pb;
            const float n1 = (a1 + a0 + (sk1 ? p3 : 0.0f)) * pl1;
            const float n2 = (a2 + a1) * pb;
            a4 = (a4 + a3) * pb;            // real only on lane31; junk benign
            a0 = n0; a1 = n1; a2 = n2; a3 = n3;
            p3 = (lane == 0) ? 0.0f : t3;
        };
        // Renorm to keep magnitudes in normal f32 range (probs can be tiny).
        auto renorm = [&]() {
            float m = fmaxf(fmaxf(a0, a1), fmaxf(fmaxf(a2, a3), a4));
            const unsigned gmax = warp_max_u32(__float_as_uint(m));
            if (gmax) {
                const int e = (int)(gmax >> 23);
                E += e - 127;
                const float sc = __uint_as_float((unsigned)(254 - e) << 23);
                a0 *= sc; a1 *= sc; a2 *= sc; a3 *= sc; a4 *= sc;
                p3 *= sc;                   // carried neighbor value too
            }
        };

        float C0[8], C1[8], C2[8], N0[8], N1[8], N2[8];
        int t = 1;
        const int ngroups = (len - 1) >> 3;

        if (ngroups > 0) {
            #pragma unroll
            for (int i = 0; i < 8; ++i) {
                const float* r = sp + (1 + i) * LPW;
                C0[i] = r[0]; C1[i] = r[j1]; C2[i] = r[j2];
            }
        }
        #pragma unroll 1
        for (int g = 0; g < ngroups; ++g) {
            if (g + 1 < ngroups) {                  // prefetch next group
                #pragma unroll
                for (int i = 0; i < 8; ++i) {
                    const float* r = sp + (t + 8 + i) * LPW;
                    N0[i] = r[0]; N1[i] = r[j1]; N2[i] = r[j2];
                }
            }
            #pragma unroll
            for (int i = 0; i < 4; ++i) step(C0[i], C1[i], C2[i]);
            renorm();
            #pragma unroll
            for (int i = 4; i < 8; ++i) step(C0[i], C1[i], C2[i]);
            renorm();

            #pragma unroll
            for (int i = 0; i < 8; ++i) { C0[i] = N0[i]; C1[i] = N1[i]; C2[i] = N2[i]; }
            t += 8;
        }
        #pragma unroll 1
        for (; t < len; ++t) {                      // <=7 tail steps
            const float* r = sp + t * LPW;
            step(r[0], r[j1], r[j2]);
            if (((t - 1) & 3) == 3) renorm();
        }

        // Stash alphas in smem (slab no longer needed) and finalize.
        __syncwarp();
        sp[4 * lane + 0] = a0;
        sp[4 * lane + 1] = a1;
        sp[4 * lane + 2] = a2;
        sp[4 * lane + 3] = a3;
        if (lane == 31) sp[128] = a4;
        __syncwarp();

        if (lane == 0) {
            int hi = 2 * __ldg(&target_len[b]);
            if (hi > L_DIM - 1) hi = L_DIM - 1;
            int lo = hi - 1; if (lo < 0) lo = 0;
            const float sum = sp[hi] + sp[lo];
            float v = -(lg2(sum) + (float)E) * LN2;
            if (!isfinite(v) || v > 1e29f || sum <= 0.0f) v = 0.0f;
            g_nll[b] = v;

            __threadfence();
            const int old = atomicAdd(&g_done, 1);
            if (old == B_DIM - 1) {                 // last block: reduce
                __threadfence();
                float s = 0.0f;
                #pragma unroll
                for (int i = 0; i < B_DIM; ++i)
                    s += ((volatile float*)g_nll)[i];
                out[0] = s;
                g_done = 0;                         // reset for next replay
            }
        }
    }
}

extern "C" void kernel_launch(void* const* d_in, const int* in_sizes, int n_in,
                              void* d_out, int out_size) {
    const float* acts   = (const float*)d_in[0];
    const int*   labels = (const int*)d_in[1];
    const int*   ilen   = (const int*)d_in[2];
    const int*   tlen   = (const int*)d_in[3];
    (void)in_sizes; (void)n_in; (void)out_size;

    const int smem_bytes = T_DIM * LPW * (int)sizeof(float);   // 133120
    cudaFuncSetAttribute(k_alpha, cudaFuncAttributeMaxDynamicSharedMemorySize,
                         smem_bytes);

    k_lse_gather<<<T_DIM * B_DIM, 256>>>(acts, labels, ilen);
    k_alpha<<<B_DIM, 128, smem_bytes>>>(labels, ilen, tlen, (float*)d_out);
}

// round 9
// speedup vs baseline: 1.9038x; 1.1977x over previous
#include <cuda_runtime.h>
#include <math.h>

#define T_DIM 512
#define B_DIM 32
#define V_DIM 4096
#define S_DIM 64
#define L_DIM 129              // 2*S + 1
#define LPW   65               // probs per (b,t): blank + 64 labels
#define PRESCALE 14.0f         // probs stored as p * 2^14 (keeps renorm-8 safe)

#define LOG2E 1.4426950408889634f
#define LN2   0.6931471805599453f

// Scratch (zero-init at load; g_done reset in-kernel each run).
__device__ float g_p[(size_t)B_DIM * T_DIM * LPW];
__device__ float g_nll[B_DIM];
__device__ int   g_done;

__device__ __forceinline__ float ex2(float x) {
    float y; asm("ex2.approx.f32 %0, %1;" : "=f"(y) : "f"(x)); return y;
}
__device__ __forceinline__ float lg2(float x) {
    float y; asm("lg2.approx.f32 %0, %1;" : "=f"(y) : "f"(x)); return y;
}
__device__ __forceinline__ unsigned warp_max_u32(unsigned v) {
    unsigned r;
    asm("redux.sync.max.u32 %0, %1, 0xffffffff;" : "=r"(r) : "r"(v));
    return r;
}

// ---------------------------------------------------------------------------
// Kernel 1: per (t,b) row: one-pass sum(exp) + gather 65 prescaled probs.
// Rows with t >= input_len[b] are never consumed -> skipped (~25% DRAM).
// ---------------------------------------------------------------------------
__global__ __launch_bounds__(256) void k_lse_gather(
    const float* __restrict__ acts, const int* __restrict__ labels,
    const int* __restrict__ input_len) {
    const int row = blockIdx.x;            // t*B + b
    const int t   = row / B_DIM;
    const int b   = row - t * B_DIM;
    if (t >= __ldg(&input_len[b])) return; // dead row

    const float* __restrict__ x = acts + (size_t)row * V_DIM;
    const int tid = threadIdx.x;

    const float4* __restrict__ x4 = reinterpret_cast<const float4*>(x);
    float s = 0.0f;
    #pragma unroll
    for (int k = 0; k < 4; ++k) {
        float4 r = __ldcs(&x4[tid + 256 * k]);   // stream, evict-first
        s += ex2(r.x * LOG2E) + ex2(r.y * LOG2E)
           + ex2(r.z * LOG2E) + ex2(r.w * LOG2E);
    }

    __shared__ float s_s[8];
    __shared__ float s_bcast;
    #pragma unroll
    for (int o = 16; o; o >>= 1) s += __shfl_xor_sync(0xffffffffu, s, o);
    if ((tid & 31) == 0) s_s[tid >> 5] = s;
    __syncthreads();
    if (tid < 32) {
        float v = (tid < 8) ? s_s[tid] : 0.0f;
        #pragma unroll
        for (int o = 4; o; o >>= 1) v += __shfl_xor_sync(0xffffffffu, v, o);
        if (tid == 0) s_bcast = lg2(v);
    }
    __syncthreads();
    const float log2sum = s_bcast;

    if (tid < LPW) {
        const int cls = (tid == 0) ? 0 : __ldg(&labels[b * S_DIM + tid - 1]);
        g_p[((size_t)b * T_DIM + t) * LPW + tid] =
            ex2(x[cls] * LOG2E - log2sum + PRESCALE);
    }
}

// ---------------------------------------------------------------------------
// Kernel 2: scaled linear-domain CTC alpha, one block per batch.
// Named-register 2-step LDS pipeline (no spilling), float-mask FFMAs instead
// of selects, off-chain pair sums (s01, s23). Cross-lane chain per 2 steps:
// shfl(26) + 8 + 8 = 21 cyc/step. Branchless renorm every 8 steps (safe via
// 2^14 prob prescale). Last block reduces the 32 NLLs into out[0].
// ---------------------------------------------------------------------------
__global__ __launch_bounds__(128) void k_alpha(
    const int* __restrict__ labels,
    const int* __restrict__ input_len,
    const int* __restrict__ target_len,
    float* __restrict__ out) {
    extern __shared__ float sp[];                 // (T_DIM+4) * LPW floats
    const int b   = blockIdx.x;
    const int tid = threadIdx.x;
    const int len = __ldg(&input_len[b]);

    // Cooperative preload of live rows [0, len).
    {
        const float4* __restrict__ src =
            reinterpret_cast<const float4*>(g_p + (size_t)b * T_DIM * LPW);
        float4* dst = reinterpret_cast<float4*>(sp);
        const int n4 = (len * LPW + 3) >> 2;
        #pragma unroll 4
        for (int i = tid; i < n4; i += 128) dst[i] = src[i];
    }
    __syncthreads();

    if (tid < 32) {
        const int lane = tid;
        const int j1 = 2 * lane + 1;
        const int j2 = 2 * lane + 2;
        const int* lab = labels + b * S_DIM;
        // Float masks: fold lane-0 and skip conditions into FFMAs.
        const float m0   = (lane == 0) ? 0.0f : 1.0f;
        const float sk1f = ((lane >= 1) &&
            (__ldg(&lab[2 * lane]) != __ldg(&lab[2 * lane - 1]))) ? 1.0f : 0.0f;
        const float sk3f =
            (__ldg(&lab[2 * lane + 1]) != __ldg(&lab[2 * lane])) ? 1.0f : 0.0f;

        float a0 = (lane == 0) ? sp[0] : 0.0f;
        float a1 = (lane == 0) ? sp[1] : 0.0f;
        float a2 = 0.0f, a3 = 0.0f, a4 = 0.0f;
        float p3 = 0.0f;                  // neighbor's a3 (0 at t=0)
        float s01 = a0 + a1;              // pair sums, maintained off-chain
        float s23 = 0.0f;
        int   E  = 0;

        // One timestep. Chain: p3 -> n1 -> (next) n3 -> shfl -> p3.
        auto step = [&](float pb, float q, float r) {
            const float n3 = fmaf(a1, sk3f, s23) * r;
            const float t3 = __shfl_up_sync(0xffffffffu, n3, 1);
            const float n0 = fmaf(p3, m0, a0) * pb;
            const float n1 = fmaf(p3, sk1f, s01) * q;
            const float n2 = (a2 + a1) * pb;
            a4 = (a4 + a3) * pb;          // real only on lane31; junk benign
            s01 = n0 + n1;
            s23 = n2 + n3;
            a0 = n0; a1 = n1; a2 = n2; a3 = n3;
            p3 = t3;                      // lane0 lands junk; masked by m0/sk1f
        };
        // Branchless renorm (exact power-of-2). Scales ALL carried state.
        auto renorm = [&]() {
            float m = fmaxf(fmaxf(a0, a1), fmaxf(fmaxf(a2, a3), a4));
            const unsigned gmax = warp_max_u32(__float_as_uint(m));
            const int e = (int)(gmax >> 23);
            E += e - 127;
            const float sc = __uint_as_float((unsigned)(254 - e) << 23);
            a0 *= sc; a1 *= sc; a2 *= sc; a3 *= sc; a4 *= sc;
            p3 *= sc; s01 *= sc; s23 *= sc;
        };

        const int nsteps = len - 1;                 // steps t = 1..len-1
        const int ngr    = nsteps >> 3;             // groups of 8
        int t = 1;

        // 2-step named-register pipeline (current rows t, t+1).
        float pb0, q0, r0, pb1, q1, r1;
        if (ngr > 0) {
            const float* ra = sp + 1 * LPW;
            const float* rb = sp + 2 * LPW;
            pb0 = ra[0]; q0 = ra[j1]; r0 = ra[j2];
            pb1 = rb[0]; q1 = rb[j1]; r1 = rb[j2];
        }
        #pragma unroll 1
        for (int g = 0; g < ngr; ++g) {
            #pragma unroll
            for (int u = 0; u < 4; ++u) {           // 4 units x 2 steps
                const float* ra = sp + (t + 2) * LPW;   // prefetch 2 ahead
                const float* rb = sp + (t + 3) * LPW;
                const float npb0 = ra[0], nq0 = ra[j1], nr0 = ra[j2];
                const float npb1 = rb[0], nq1 = rb[j1], nr1 = rb[j2];
                step(pb0, q0, r0);
                step(pb1, q1, r1);
                pb0 = npb0; q0 = nq0; r0 = nr0;
                pb1 = npb1; q1 = nq1; r1 = nr1;
                t += 2;
            }
            renorm();
        }
        #pragma unroll 1
        for (; t < len; ++t) {                      // <=7 tail steps
            const float* r = sp + t * LPW;
            step(r[0], r[j1], r[j2]);
            renorm();
        }

        // Stash alphas in smem (slab no longer needed) and finalize.
        __syncwarp();
        sp[4 * lane + 0] = a0;
        sp[4 * lane + 1] = a1;
        sp[4 * lane + 2] = a2;
        sp[4 * lane + 3] = a3;
        if (lane == 31) sp[128] = a4;
        __syncwarp();

        if (lane == 0) {
            int hi = 2 * __ldg(&target_len[b]);
            if (hi > L_DIM - 1) hi = L_DIM - 1;
            int lo = hi - 1; if (lo < 0) lo = 0;
            const float sum = sp[hi] + sp[lo];
            // alpha_true = sum * 2^(E) * 2^(-PRESCALE*len)
            float v = -(lg2(sum) + (float)E - PRESCALE * (float)len) * LN2;
            if (!isfinite(v) || v > 1e29f || sum <= 0.0f) v = 0.0f;
            g_nll[b] = v;

            __threadfence();
            const int old = atomicAdd(&g_done, 1);
            if (old == B_DIM - 1) {                 // last block: reduce
                __threadfence();
                float s = 0.0f;
                #pragma unroll
                for (int i = 0; i < B_DIM; ++i)
                    s += ((volatile float*)g_nll)[i];
                out[0] = s;
                g_done = 0;                         // reset for next replay
            }
        }
    }
}

extern "C" void kernel_launch(void* const* d_in, const int* in_sizes, int n_in,
                              void* d_out, int out_size) {
    const float* acts   = (const float*)d_in[0];
    const int*   labels = (const int*)d_in[1];
    const int*   ilen   = (const int*)d_in[2];
    const int*   tlen   = (const int*)d_in[3];
    (void)in_sizes; (void)n_in; (void)out_size;

    // +4 rows of slack so the 2-ahead prefetch never reads out of bounds.
    const int smem_bytes = (T_DIM + 4) * LPW * (int)sizeof(float);
    cudaFuncSetAttribute(k_alpha, cudaFuncAttributeMaxDynamicSharedMemorySize,
                         smem_bytes);

    k_lse_gather<<<T_DIM * B_DIM, 256>>>(acts, labels, ilen);
    k_alpha<<<B_DIM, 128, smem_bytes>>>(labels, ilen, tlen, (float*)d_out);
}